// round 4
// baseline (speedup 1.0000x reference)
#include <cuda_runtime.h>

// x [8, 65536, 256] fp32 -> per-sample classical Gram-Schmidt over 8 vectors.
// R3: 2 warps per sample (each owns a 128-dim half, 1 float4/vector/lane =
// 32 data floats/lane) to cut registers ~80 -> ~50 and raise occupancy
// 33% -> ~60%. Cross-warp reductions: intra-warp shuffle then a 2-way add
// through shared memory guarded by a per-pair named barrier (64 threads).

#define NSAMP 65536
#define NDIM  256
#define NMOD  8

__device__ __forceinline__ float warp_sum(float v) {
#pragma unroll
    for (int o = 16; o; o >>= 1)
        v += __shfl_xor_sync(0xffffffffu, v, o);
    return v;
}

__device__ __forceinline__ float dot4(const float4& p, const float4& q) {
    return p.x * q.x + p.y * q.y + p.z * q.z + p.w * q.w;
}

__device__ __forceinline__ void pair_bar(int id) {
    asm volatile("bar.sync %0, %1;" :: "r"(id), "r"(64) : "memory");
}

__global__ __launch_bounds__(256)
void gram_schmidt_kernel(const float* __restrict__ x, float* __restrict__ out) {
    const int tid  = threadIdx.x;
    const int warp = tid >> 5;      // 0..7
    const int lane = tid & 31;
    const int pair = warp >> 1;     // 0..3: sample slot within block
    const int half = warp & 1;      // which 128-dim half this warp owns
    const int samp = blockIdx.x * 4 + pair;

    // [pair][half][slot]: slots 0..7 = projection partials, slot 8 = norm partial
    __shared__ float red[4][2][NMOD + 1];

    const size_t model_stride = (size_t)NSAMP * NDIM;
    const size_t base_off = (size_t)samp * NDIM + half * 128 + 4 * lane;
    const float* base = x + base_off;
    const int bid = pair + 1;       // named barrier id for this sample pair

    // Load this warp's half of all 8 vectors (8 independent LDG.128.CS).
    float4 a[NMOD];
#pragma unroll
    for (int i = 0; i < NMOD; i++)
        a[i] = __ldcs(reinterpret_cast<const float4*>(base + i * model_stride));

#pragma unroll
    for (int i = 0; i < NMOD; i++) {
        if (i > 0) {
            // Round 1: projection coefficients of ORIGINAL a[i] onto basis 0..i-1
            // (classical GS — all dots before any subtraction).
#pragma unroll
            for (int k = 0; k < NMOD; k++) {
                if (k < i) {
                    float w = warp_sum(dot4(a[i], a[k]));
                    if (lane == 0) red[pair][half][k] = w;
                }
            }
            pair_bar(bid);
            float c[NMOD];
#pragma unroll
            for (int k = 0; k < NMOD; k++)
                if (k < i) c[k] = red[pair][0][k] + red[pair][1][k];
#pragma unroll
            for (int k = 0; k < NMOD; k++) {
                if (k < i) {
                    a[i].x -= c[k] * a[k].x;
                    a[i].y -= c[k] * a[k].y;
                    a[i].z -= c[k] * a[k].z;
                    a[i].w -= c[k] * a[k].w;
                }
            }
        }
        // Round 2: normalize.
        float n = warp_sum(dot4(a[i], a[i]));
        if (lane == 0) red[pair][half][NMOD] = n;
        pair_bar(bid);
        float inv = rsqrtf(red[pair][0][NMOD] + red[pair][1][NMOD]);
        a[i].x *= inv; a[i].y *= inv; a[i].z *= inv; a[i].w *= inv;

        // Store this basis vector half (coalesced STG.128.CS).
        __stcs(reinterpret_cast<float4*>(out + base_off + i * model_stride), a[i]);
    }
}

extern "C" void kernel_launch(void* const* d_in, const int* in_sizes, int n_in,
                              void* d_out, int out_size) {
    const float* x = (const float*)d_in[0];
    float* out = (float*)d_out;
    // 4 samples per 256-thread block (2 warps per sample) -> 16384 blocks.
    gram_schmidt_kernel<<<NSAMP / 4, 256>>>(x, out);
}

// round 5
// speedup vs baseline: 1.1543x; 1.1543x over previous
#include <cuda_runtime.h>

// x [8, 65536, 256] fp32 -> per-sample classical Gram-Schmidt over 8 vectors.
// R4: back to 1 warp/sample (R3's 2-warp split saturated the MIO/L1 path).
// New: remove the per-step norm reduction from the critical chain using
//   ||w||^2 = ||v||^2 - sum_k c_k^2   (basis orthonormal),
// with all 8 ||v_i||^2 warp-reductions hoisted to the front where they overlap
// load latency. Critical path per GS step: one shuffle-reduction deep.

#define NSAMP 65536
#define NDIM  256
#define NMOD  8

__device__ __forceinline__ float warp_sum(float v) {
#pragma unroll
    for (int o = 16; o; o >>= 1)
        v += __shfl_xor_sync(0xffffffffu, v, o);
    return v;
}

__device__ __forceinline__ float dot8(const float4& p0, const float4& p1,
                                      const float4& q0, const float4& q1) {
    return p0.x * q0.x + p0.y * q0.y + p0.z * q0.z + p0.w * q0.w
         + p1.x * q1.x + p1.y * q1.y + p1.z * q1.z + p1.w * q1.w;
}

__global__ __launch_bounds__(256)
void gram_schmidt_kernel(const float* __restrict__ x, float* __restrict__ out) {
    const int warp = (blockIdx.x * blockDim.x + threadIdx.x) >> 5;
    const int lane = threadIdx.x & 31;

    const size_t samp_off     = (size_t)warp * NDIM;
    const size_t model_stride = (size_t)NSAMP * NDIM;
    const int d0 = 4 * lane;        // dims [d0, d0+4)
    const int d1 = 128 + 4 * lane;  // dims [d1, d1+4)

    // Load all 8 vectors up front (16 independent LDG.128.CS -> deep MLP).
    float4 a[NMOD][2];
#pragma unroll
    for (int i = 0; i < NMOD; i++) {
        const float* p = x + (size_t)i * model_stride + samp_off;
        a[i][0] = __ldcs(reinterpret_cast<const float4*>(p + d0));
        a[i][1] = __ldcs(reinterpret_cast<const float4*>(p + d1));
    }

    // Hoisted self-norms: 8 independent reductions, pipelined while the
    // later loads are still in flight.
    float n2[NMOD];
#pragma unroll
    for (int i = 0; i < NMOD; i++)
        n2[i] = warp_sum(dot8(a[i][0], a[i][1], a[i][0], a[i][1]));

#pragma unroll
    for (int i = 0; i < NMOD; i++) {
        float w2 = n2[i];  // running ||w||^2 = ||v||^2 - sum c_k^2
        if (i > 0) {
            // Classical GS: all coefficients against ORIGINAL v_i, computed
            // in parallel (independent shuffle chains, one reduction deep).
            float c[NMOD];
#pragma unroll
            for (int k = 0; k < NMOD; k++) {
                if (k < i) {
                    float p = dot8(a[i][0], a[i][1], a[k][0], a[k][1]);
                    c[k] = warp_sum(p);
                }
            }
#pragma unroll
            for (int k = 0; k < NMOD; k++) {
                if (k < i) {
                    w2 -= c[k] * c[k];
                    a[i][0].x -= c[k] * a[k][0].x;
                    a[i][0].y -= c[k] * a[k][0].y;
                    a[i][0].z -= c[k] * a[k][0].z;
                    a[i][0].w -= c[k] * a[k][0].w;
                    a[i][1].x -= c[k] * a[k][1].x;
                    a[i][1].y -= c[k] * a[k][1].y;
                    a[i][1].z -= c[k] * a[k][1].z;
                    a[i][1].w -= c[k] * a[k][1].w;
                }
            }
        }
        float inv = rsqrtf(w2);
        a[i][0].x *= inv; a[i][0].y *= inv; a[i][0].z *= inv; a[i][0].w *= inv;
        a[i][1].x *= inv; a[i][1].y *= inv; a[i][1].z *= inv; a[i][1].w *= inv;

        // Store immediately (off the critical path; next step only needs regs).
        float* q = out + (size_t)i * model_stride + samp_off;
        __stcs(reinterpret_cast<float4*>(q + d0), a[i][0]);
        __stcs(reinterpret_cast<float4*>(q + d1), a[i][1]);
    }
}

extern "C" void kernel_launch(void* const* d_in, const int* in_sizes, int n_in,
                              void* d_out, int out_size) {
    const float* x = (const float*)d_in[0];
    float* out = (float*)d_out;
    // 65536 samples, 1 warp each, 8 warps (256 threads) per block -> 8192 blocks.
    gram_schmidt_kernel<<<NSAMP / 8, 256>>>(x, out);
}

// round 6
// speedup vs baseline: 1.1561x; 1.0016x over previous
#include <cuda_runtime.h>

// x [8, 65536, 256] fp32 -> per-sample classical Gram-Schmidt over 8 vectors.
// R5: replace the 7 SEQUENTIAL per-step coefficient reductions with
//   G = X X^T  (36 INDEPENDENT warp reductions, one reduction-depth total)
//   G = L L^T  (8x8 Cholesky, per-lane replicated register math)
//   b_i = (v_i - sum_{j<i} L_ij b_j) / L_ii   (forward substitution, no reductions)
// which is algebraically exact classical Gram-Schmidt (L_ij = <v_i, b_j>).
// Critical path: ~1 reduction + ~250cyc scalar Cholesky vs ~7 reductions before.

#define NSAMP 65536
#define NDIM  256
#define NMOD  8
#define TRI(i, j) ((i) * ((i) + 1) / 2 + (j))

__device__ __forceinline__ float warp_sum(float v) {
#pragma unroll
    for (int o = 16; o; o >>= 1)
        v += __shfl_xor_sync(0xffffffffu, v, o);
    return v;
}

__device__ __forceinline__ float dot8(const float4& p0, const float4& p1,
                                      const float4& q0, const float4& q1) {
    return p0.x * q0.x + p0.y * q0.y + p0.z * q0.z + p0.w * q0.w
         + p1.x * q1.x + p1.y * q1.y + p1.z * q1.z + p1.w * q1.w;
}

__global__ __launch_bounds__(256)
void gram_schmidt_kernel(const float* __restrict__ x, float* __restrict__ out) {
    const int warp = (blockIdx.x * blockDim.x + threadIdx.x) >> 5;
    const int lane = threadIdx.x & 31;

    const size_t samp_off     = (size_t)warp * NDIM;
    const size_t model_stride = (size_t)NSAMP * NDIM;
    const int d0 = 4 * lane;        // dims [d0, d0+4)
    const int d1 = 128 + 4 * lane;  // dims [d1, d1+4)

    // Load all 8 vectors (16 independent LDG.128.CS -> deep MLP).
    float4 a[NMOD][2];
#pragma unroll
    for (int i = 0; i < NMOD; i++) {
        const float* p = x + (size_t)i * model_stride + samp_off;
        a[i][0] = __ldcs(reinterpret_cast<const float4*>(p + d0));
        a[i][1] = __ldcs(reinterpret_cast<const float4*>(p + d1));
    }

    // Gram matrix, lower triangle: 36 INDEPENDENT warp reductions that
    // pipeline with each other and with the in-flight loads.
    float L[TRI(NMOD - 1, NMOD - 1) + 1];  // 36, overwritten by Cholesky factor
#pragma unroll
    for (int i = 0; i < NMOD; i++)
#pragma unroll
        for (int j = 0; j <= i; j++)
            L[TRI(i, j)] = warp_sum(dot8(a[i][0], a[i][1], a[j][0], a[j][1]));

    // In-register 8x8 Cholesky G = L L^T (same scalars in every lane).
    // invd[i] = 1/L_ii kept for the substitution scale.
    float invd[NMOD];
#pragma unroll
    for (int i = 0; i < NMOD; i++) {
#pragma unroll
        for (int j = 0; j <= i; j++) {
            float s = L[TRI(i, j)];
#pragma unroll
            for (int m = 0; m < NMOD; m++)
                if (m < j) s -= L[TRI(i, m)] * L[TRI(j, m)];
            if (j == i) {
                invd[i] = rsqrtf(s);
                L[TRI(i, i)] = s * invd[i];  // = sqrt(s), not used later
            } else {
                L[TRI(i, j)] = s * invd[j];  // = <v_i, b_j> (classical GS coeff)
            }
        }
    }

    // Forward substitution: b_i = (v_i - sum_{j<i} L_ij b_j) * invd[i].
    // a[] is overwritten in place with the normalized basis.
#pragma unroll
    for (int i = 0; i < NMOD; i++) {
#pragma unroll
        for (int j = 0; j < NMOD; j++) {
            if (j < i) {
                const float c = L[TRI(i, j)];
                a[i][0].x -= c * a[j][0].x;
                a[i][0].y -= c * a[j][0].y;
                a[i][0].z -= c * a[j][0].z;
                a[i][0].w -= c * a[j][0].w;
                a[i][1].x -= c * a[j][1].x;
                a[i][1].y -= c * a[j][1].y;
                a[i][1].z -= c * a[j][1].z;
                a[i][1].w -= c * a[j][1].w;
            }
        }
        const float inv = invd[i];
        a[i][0].x *= inv; a[i][0].y *= inv; a[i][0].z *= inv; a[i][0].w *= inv;
        a[i][1].x *= inv; a[i][1].y *= inv; a[i][1].z *= inv; a[i][1].w *= inv;

        float* q = out + (size_t)i * model_stride + samp_off;
        __stcs(reinterpret_cast<float4*>(q + d0), a[i][0]);
        __stcs(reinterpret_cast<float4*>(q + d1), a[i][1]);
    }
}

extern "C" void kernel_launch(void* const* d_in, const int* in_sizes, int n_in,
                              void* d_out, int out_size) {
    const float* x = (const float*)d_in[0];
    float* out = (float*)d_out;
    // 65536 samples, 1 warp each, 8 warps (256 threads) per block -> 8192 blocks.
    gram_schmidt_kernel<<<NSAMP / 8, 256>>>(x, out);
}

// round 8
// speedup vs baseline: 1.1673x; 1.0097x over previous
#include <cuda_runtime.h>
#include <cuda_pipeline.h>

// x [8, 65536, 256] fp32 -> per-sample classical Gram-Schmidt over 8 vectors.
// R6: R5's Cholesky formulation (G = XX^T -> LL^T -> forward substitution,
// algebraically exact classical GS) + cp.async software pipelining:
// each warp handles 4 samples; sample k+1 streams DRAM->smem (LDGSTS, no
// destination registers) while sample k is computed from registers. Loads
// stay outstanding through the compute phase -> DRAM duty cycle ~continuous.

#define NSAMP 65536
#define NDIM  256
#define NMOD  8
#define WPB   4                    // warps per block
#define SPW   4                    // samples per warp
#define TOTAL_WARPS (NSAMP / SPW)  // 16384
#define TRI(i, j) ((i) * ((i) + 1) / 2 + (j))

__device__ __forceinline__ float warp_sum(float v) {
#pragma unroll
    for (int o = 16; o; o >>= 1)
        v += __shfl_xor_sync(0xffffffffu, v, o);
    return v;
}

__device__ __forceinline__ float dot8(const float4& p0, const float4& p1,
                                      const float4& q0, const float4& q1) {
    return p0.x * q0.x + p0.y * q0.y + p0.z * q0.z + p0.w * q0.w
         + p1.x * q1.x + p1.y * q1.y + p1.z * q1.z + p1.w * q1.w;
}

__device__ __forceinline__ void prefetch_sample(
    float4 (*buf)[2][32], const float* __restrict__ x,
    size_t samp, int lane) {
    const size_t model_stride = (size_t)NSAMP * NDIM;
    const float* p = x + samp * NDIM;
#pragma unroll
    for (int i = 0; i < NMOD; i++) {
        const float* v = p + i * model_stride;
        __pipeline_memcpy_async(&buf[i][0][lane], v + 4 * lane, 16);
        __pipeline_memcpy_async(&buf[i][1][lane], v + 128 + 4 * lane, 16);
    }
}

__global__ __launch_bounds__(128, 4)
void gram_schmidt_kernel(const float* __restrict__ x, float* __restrict__ out) {
    const int wib  = threadIdx.x >> 5;
    const int lane = threadIdx.x & 31;
    const int gwarp = blockIdx.x * WPB + wib;

    // 8 KB staging buffer per warp (one sample), 32 KB static per block.
    __shared__ float4 buf[WPB][NMOD][2][32];
    float4 (*mybuf)[2][32] = buf[wib];

    const size_t model_stride = (size_t)NSAMP * NDIM;
    const int d0 = 4 * lane;
    const int d1 = 128 + 4 * lane;

    // Prologue: stage sample 0.
    prefetch_sample(mybuf, x, (size_t)gwarp, lane);
    __pipeline_commit();

    for (int it = 0; it < SPW; it++) {
        const size_t samp = (size_t)gwarp + (size_t)it * TOTAL_WARPS;
        const size_t samp_off = samp * NDIM;

        // Wait for this sample's staged data, pull into registers.
        __pipeline_wait_prior(0);
        float4 a[NMOD][2];
#pragma unroll
        for (int i = 0; i < NMOD; i++) {
            a[i][0] = mybuf[i][0][lane];
            a[i][1] = mybuf[i][1][lane];
        }

        float L[TRI(NMOD - 1, NMOD - 1) + 1];  // Gram lower triangle -> Cholesky

        // Diagonal dots FIRST: consuming every element of a[] guarantees all
        // LDS reads completed before the next cp.async overwrites the buffer.
#pragma unroll
        for (int i = 0; i < NMOD; i++)
            L[TRI(i, i)] = warp_sum(dot8(a[i][0], a[i][1], a[i][0], a[i][1]));

        // Kick off the next sample's DRAM->smem stream; it lands during the
        // ~1000 cycles of Gram/Cholesky/substitution below.
        if (it + 1 < SPW) {
            prefetch_sample(mybuf, x, (size_t)gwarp + (size_t)(it + 1) * TOTAL_WARPS, lane);
            __pipeline_commit();
        }

        // Off-diagonal Gram entries: 28 independent warp reductions.
#pragma unroll
        for (int i = 1; i < NMOD; i++)
#pragma unroll
            for (int j = 0; j < i; j++)
                L[TRI(i, j)] = warp_sum(dot8(a[i][0], a[i][1], a[j][0], a[j][1]));

        // In-register 8x8 Cholesky G = L L^T (replicated per lane).
        float invd[NMOD];
#pragma unroll
        for (int i = 0; i < NMOD; i++) {
#pragma unroll
            for (int j = 0; j <= i; j++) {
                float s = L[TRI(i, j)];
#pragma unroll
                for (int m = 0; m < NMOD; m++)
                    if (m < j) s -= L[TRI(i, m)] * L[TRI(j, m)];
                if (j == i) {
                    invd[i] = rsqrtf(s);
                    L[TRI(i, i)] = s * invd[i];
                } else {
                    L[TRI(i, j)] = s * invd[j];  // = <v_i, b_j>
                }
            }
        }

        // Forward substitution: b_i = (v_i - sum_{j<i} L_ij b_j) * invd[i].
#pragma unroll
        for (int i = 0; i < NMOD; i++) {
#pragma unroll
            for (int j = 0; j < NMOD; j++) {
                if (j < i) {
                    const float c = L[TRI(i, j)];
                    a[i][0].x -= c * a[j][0].x;
                    a[i][0].y -= c * a[j][0].y;
                    a[i][0].z -= c * a[j][0].z;
                    a[i][0].w -= c * a[j][0].w;
                    a[i][1].x -= c * a[j][1].x;
                    a[i][1].y -= c * a[j][1].y;
                    a[i][1].z -= c * a[j][1].z;
                    a[i][1].w -= c * a[j][1].w;
                }
            }
            const float inv = invd[i];
            a[i][0].x *= inv; a[i][0].y *= inv; a[i][0].z *= inv; a[i][0].w *= inv;
            a[i][1].x *= inv; a[i][1].y *= inv; a[i][1].z *= inv; a[i][1].w *= inv;

            float* q = out + (size_t)i * model_stride + samp_off;
            __stcs(reinterpret_cast<float4*>(q + d0), a[i][0]);
            __stcs(reinterpret_cast<float4*>(q + d1), a[i][1]);
        }
    }
}

extern "C" void kernel_launch(void* const* d_in, const int* in_sizes, int n_in,
                              void* d_out, int out_size) {
    const float* x = (const float*)d_in[0];
    float* out = (float*)d_out;
    // 16384 warps x 4 samples; 4 warps (128 threads) per block -> 4096 blocks.
    gram_schmidt_kernel<<<TOTAL_WARPS / WPB, 128>>>(x, out);
}